// round 16
// baseline (speedup 1.0000x reference)
#include <cuda_runtime.h>
#include <math.h>
#include <stdint.h>

#define BB 32
#define SS 512
#define HH 768
#define NHH 8
#define HDD 96
#define SEPTOK 102
#define RCH 6   // row chunks for streaming pass
#define SCH 4   // row chunks for softmaxw

// ---------------- scratch ----------------
__device__ int   g_s1[BB], g_s2[BB];
__device__ float g_xfeat[BB][HH];
__device__ float g_sdiff[BB][HH];
__device__ float g_Q[BB][SS][HH];
__device__ float g_K[BB][SS][HH];
__device__ float g_wbp[BB][NHH][16][256];
__device__ float g_whp[BB][SCH][SS];
__device__ float g_wpp[BB][SCH][256];
__device__ float g_u[BB][NHH][HH];
__device__ float g_sim[BB][256][SS];
__device__ float g_simT[BB][SS][256];
__device__ float g_al[BB][2 * HH];
__device__ float g_ps[BB][RCH][4][HH];
__device__ float g_pu[BB][RCH][NHH][HH];
__device__ float g_pa[BB][RCH][2][HH];
__device__ float g_feat[BB][128];
__device__ float g_diff[BB][128];
__device__ float g_attnr[BB][128];
__device__ float g_alignr[BB][128];

__device__ __forceinline__ float telu_f(float x) {
    return x * tanhf(__expf(x));
}

__device__ __forceinline__ float f2tf(float x) {
    uint32_t u;
    asm("cvt.rna.tf32.f32 %0, %1;" : "=r"(u) : "f"(x));
    return __uint_as_float(u);
}

__device__ __forceinline__ void mma_tf32(float* d, const float* a, const float* bfr) {
    asm volatile(
        "mma.sync.aligned.m16n8k8.row.col.f32.tf32.tf32.f32 "
        "{%0,%1,%2,%3}, {%4,%5,%6,%7}, {%8,%9}, {%0,%1,%2,%3};"
        : "+f"(d[0]), "+f"(d[1]), "+f"(d[2]), "+f"(d[3])
        : "r"(__float_as_uint(a[0])), "r"(__float_as_uint(a[1])),
          "r"(__float_as_uint(a[2])), "r"(__float_as_uint(a[3])),
          "r"(__float_as_uint(bfr[0])), "r"(__float_as_uint(bfr[1])));
}

__device__ __forceinline__ void cp16(void* smem_dst, const void* gsrc) {
    uint32_t d = (uint32_t)__cvta_generic_to_shared(smem_dst);
    asm volatile("cp.async.cg.shared.global [%0], [%1], 16;" :: "r"(d), "l"(gsrc));
}

// ---------------- kernel 1: find SEP positions ----------------
__global__ void k_sep(const int* __restrict__ ids) {
    int b = blockIdx.x, t = threadIdx.x;
    __shared__ int smn[128], smx[128];
    int mn = SS, mx = -1;
    for (int s = t; s < SS; s += 128) {
        int v = ids[b * SS + s];
        if (v == SEPTOK) { if (s < mn) mn = s; if (s > mx) mx = s; }
    }
    smn[t] = mn; smx[t] = mx; __syncthreads();
    for (int o = 64; o; o >>= 1) {
        if (t < o) { smn[t] = min(smn[t], smn[t + o]); smx[t] = max(smx[t], smx[t + o]); }
        __syncthreads();
    }
    if (t == 0) { g_s1[b] = smn[0]; g_s2[b] = smx[0]; }
}

// ---------------- kernel 2: masked Q/K projection, 128x128 tile, 256 thr, mt4/nt4 ----------------
__global__ void __launch_bounds__(256) k_gemm_qk(
    const float* __restrict__ hs,
    const float* __restrict__ wq, const float* __restrict__ bq,
    const float* __restrict__ wk, const float* __restrict__ bk) {
    int z = blockIdx.z;
    int mat = z & 1, b = z >> 1;
    int s1 = g_s1[b], s2 = g_s2[b];
    int r0 = blockIdx.y * 128;
    int lo = mat ? 1 : (s1 + 1);
    int hi = mat ? (s1 - 1) : (s2 - 1);
    if (r0 > hi || r0 + 127 < lo) return;
    const float* W    = mat ? wk : wq;
    const float* bias = mat ? bk : bq;
    float* out        = mat ? &g_K[b][0][0] : &g_Q[b][0][0];
    float oscale      = mat ? 1.f : 0.10206207261596575f;
    int n0 = blockIdx.x * 128;

    __shared__ __align__(16) float As[2][128][36];
    __shared__ __align__(16) float Bs[2][32][132];

    int tid = threadIdx.x;
    int lane = tid & 31, warp = tid >> 5;
    int g = lane >> 2, tig = lane & 3;
    int wm = warp >> 2, wn = warp & 3;

    float acc[4][4][4] = {};

    int ar = tid >> 3, ac = (tid & 7) * 4;
    int bkr = tid >> 4, bnc = (tid & 15) * 8;

    const float* Ab = hs + ((size_t)b * SS + r0) * HH;

    const int NCH = HH / 32;
#define QK_LOAD(st, k0)                                                              \
    do {                                                                             \
        cp16(&As[st][ar][ac],      Ab + (size_t)ar * HH + (k0) + ac);                \
        cp16(&As[st][ar + 32][ac], Ab + (size_t)(ar + 32) * HH + (k0) + ac);         \
        cp16(&As[st][ar + 64][ac], Ab + (size_t)(ar + 64) * HH + (k0) + ac);         \
        cp16(&As[st][ar + 96][ac], Ab + (size_t)(ar + 96) * HH + (k0) + ac);         \
        cp16(&Bs[st][bkr][bnc],          W + (size_t)((k0) + bkr) * HH + n0 + bnc);      \
        cp16(&Bs[st][bkr][bnc + 4],      W + (size_t)((k0) + bkr) * HH + n0 + bnc + 4);  \
        cp16(&Bs[st][bkr + 16][bnc],     W + (size_t)((k0) + bkr + 16) * HH + n0 + bnc); \
        cp16(&Bs[st][bkr + 16][bnc + 4], W + (size_t)((k0) + bkr + 16) * HH + n0 + bnc + 4); \
        asm volatile("cp.async.commit_group;");                                      \
    } while (0)

    QK_LOAD(0, 0);
    for (int chunk = 0; chunk < NCH; chunk++) {
        int st = chunk & 1;
        if (chunk + 1 < NCH) {
            QK_LOAD(st ^ 1, (chunk + 1) * 32);
            asm volatile("cp.async.wait_group 1;");
        } else {
            asm volatile("cp.async.wait_group 0;");
        }
        __syncthreads();
#pragma unroll
        for (int kk = 0; kk < 4; kk++) {
            int kb = kk * 8;
            float a[4][4];
#pragma unroll
            for (int mt = 0; mt < 4; mt++) {
                int m0 = wm * 64 + mt * 16;
                a[mt][0] = As[st][m0 + g][kb + tig];
                a[mt][1] = As[st][m0 + g + 8][kb + tig];
                a[mt][2] = As[st][m0 + g][kb + tig + 4];
                a[mt][3] = As[st][m0 + g + 8][kb + tig + 4];
            }
            float bf[4][2];
#pragma unroll
            for (int nt = 0; nt < 4; nt++) {
                int nb = wn * 32 + nt * 8;
                bf[nt][0] = Bs[st][kb + tig][nb + g];
                bf[nt][1] = Bs[st][kb + tig + 4][nb + g];
            }
#pragma unroll
            for (int mt = 0; mt < 4; mt++)
#pragma unroll
                for (int nt = 0; nt < 4; nt++)
                    mma_tf32(acc[mt][nt], a[mt], bf[nt]);
        }
        __syncthreads();
    }
#undef QK_LOAD
#pragma unroll
    for (int mt = 0; mt < 4; mt++) {
#pragma unroll
        for (int nt = 0; nt < 4; nt++) {
            int col = n0 + wn * 32 + nt * 8 + 2 * tig;
            float b0 = bias[col], b1 = bias[col + 1];
            int row0 = r0 + wm * 64 + mt * 16 + g;
            *(float2*)&out[(size_t)row0 * HH + col] =
                make_float2((acc[mt][nt][0] + b0) * oscale, (acc[mt][nt][1] + b1) * oscale);
            *(float2*)&out[(size_t)(row0 + 8) * HH + col] =
                make_float2((acc[mt][nt][2] + b0) * oscale, (acc[mt][nt][3] + b1) * oscale);
        }
    }
}

// ---------------- kernel 3: fused scores + row softmax -> wbar partials ----------------
__global__ void __launch_bounds__(256) k_score_fused() {
    int rt = blockIdx.x, h = blockIdx.y, b = blockIdx.z;
    int s1 = g_s1[b], s2 = g_s2[b];
    int r0 = rt * 32;
    if (r0 > s2 - 1 || r0 + 31 < s1 + 1) return;

    __shared__ float Aq[32][100];
    __shared__ float Bs[64][36];
    __shared__ float sc[32][260];
    __shared__ float wb[8][256];

    int tid = threadIdx.x;
    int lane = tid & 31, warp = tid >> 5;
    int g = lane >> 2, tig = lane & 3;
    int wm = warp >> 2, wn = warp & 3;

    {
        int row = tid >> 3;
        int c0 = (tid & 7) * 12;
#pragma unroll
        for (int i = 0; i < 3; i++) {
            float4 v = *(const float4*)(&g_Q[b][r0 + row][h * HDD + c0 + i * 4]);
            *(float4*)&Aq[row][c0 + i * 4] = v;
        }
    }
    for (int i = tid; i < 8 * 256; i += 256) wb[i >> 8][i & 255] = 0.f;

    int tcount = (s1 + 63) >> 6;
    int ar = tid >> 3, ac = (tid & 7) * 4;

    for (int tt = 0; tt < tcount; tt++) {
        int t0 = tt * 64;
        float acc[2][4] = {};
#pragma unroll
        for (int k0 = 0; k0 < HDD; k0 += 32) {
            __syncthreads();
#pragma unroll
            for (int rr = 0; rr < 2; rr++) {
                int r = ar + rr * 32;
                float4 v = *(const float4*)(&g_K[b][t0 + r][h * HDD + k0 + ac]);
                *(float4*)&Bs[r][ac] = v;
            }
            __syncthreads();
#pragma unroll
            for (int kk = 0; kk < 4; kk++) {
                int kb = kk * 8;
                int m0 = wm * 16;
                float a[4];
                a[0] = Aq[m0 + g][k0 + kb + tig];
                a[1] = Aq[m0 + g + 8][k0 + kb + tig];
                a[2] = Aq[m0 + g][k0 + kb + tig + 4];
                a[3] = Aq[m0 + g + 8][k0 + kb + tig + 4];
                float bf[2][2];
#pragma unroll
                for (int nt = 0; nt < 2; nt++) {
                    int nb = wn * 16 + nt * 8;
                    bf[nt][0] = Bs[nb + g][kb + tig];
                    bf[nt][1] = Bs[nb + g][kb + tig + 4];
                }
#pragma unroll
                for (int nt = 0; nt < 2; nt++)
                    mma_tf32(acc[nt], a, bf[nt]);
            }
        }
#pragma unroll
        for (int nt = 0; nt < 2; nt++) {
            int col = t0 + wn * 16 + nt * 8 + 2 * tig;
            int row0 = wm * 16 + g;
            *(float2*)&sc[row0][col]     = make_float2(acc[nt][0], acc[nt][1]);
            *(float2*)&sc[row0 + 8][col] = make_float2(acc[nt][2], acc[nt][3]);
        }
    }
    __syncthreads();

    int lo = max(r0, s1 + 1), hi = min(r0 + 32, s2);
    for (int s = lo + warp; s < hi; s += 8) {
        const float* row = &sc[s - r0][0];
        float scv[8];
        float m = -1e30f;
#pragma unroll
        for (int j = 0; j < 8; j++) {
            int k = lane + j * 32;
            scv[j] = (k >= 1 && k < s1) ? row[k] : -1e30f;
            m = fmaxf(m, scv[j]);
        }
#pragma unroll
        for (int o = 16; o; o >>= 1) m = fmaxf(m, __shfl_xor_sync(0xffffffffu, m, o));
        float sum = 0.f;
#pragma unroll
        for (int j = 0; j < 8; j++) { scv[j] = __expf(scv[j] - m); sum += scv[j]; }
#pragma unroll
        for (int o = 16; o; o >>= 1) sum += __shfl_xor_sync(0xffffffffu, sum, o);
        float inv = 1.f / sum;
#pragma unroll
        for (int j = 0; j < 8; j++) {
            int k = lane + j * 32;
            if (k >= 1 && k < s1) wb[warp][k] += scv[j] * inv;
        }
        __syncwarp();
    }
    __syncthreads();
    if (tid < 256) {
        float a = 0.f;
#pragma unroll
        for (int r = 0; r < 8; r++) a += wb[r][tid];
        g_wbp[b][h][rt][tid] = a;
    }
}

// ---------------- kernel 4: sim 64x128 tile, mt2/nt4, split-tf32 (profiled slot) ----------------
__global__ void __launch_bounds__(256) k_gemm_sim(const float* __restrict__ hs) {
    int b = blockIdx.z;
    int s1 = g_s1[b], s2 = g_s2[b];
    int p0 = blockIdx.y * 64, t0 = blockIdx.x * 128;
    if (p0 > s1 - 1) return;
    if (t0 > s2 - 1 || t0 + 127 < s1 + 1) return;

    __shared__ float Ah[64][36], Al[64][36];
    __shared__ float Bh[128][36], Bl[128][36];

    int tid = threadIdx.x;
    int lane = tid & 31, warp = tid >> 5;
    int g = lane >> 2, tig = lane & 3;
    int wm = warp >> 2, wn = warp & 3;   // 2 x 4; warp tile 32 x 32

    float acc[2][4][4] = {};

    int ar = tid >> 3, ac = (tid & 7) * 4;
    const float* Ab = hs + ((size_t)b * SS + p0) * HH;
    const float* Bb = hs + ((size_t)b * SS + t0) * HH;

    for (int k0 = 0; k0 < HH; k0 += 32) {
#pragma unroll
        for (int rr = 0; rr < 2; rr++) {
            int r = ar + rr * 32;
            float4 v = *(const float4*)(Ab + (size_t)r * HH + k0 + ac);
            float4 h4, l4;
            h4.x = f2tf(v.x); l4.x = f2tf(v.x - h4.x);
            h4.y = f2tf(v.y); l4.y = f2tf(v.y - h4.y);
            h4.z = f2tf(v.z); l4.z = f2tf(v.z - h4.z);
            h4.w = f2tf(v.w); l4.w = f2tf(v.w - h4.w);
            *(float4*)&Ah[r][ac] = h4;
            *(float4*)&Al[r][ac] = l4;
        }
#pragma unroll
        for (int rr = 0; rr < 4; rr++) {
            int r = ar + rr * 32;
            float4 u4 = *(const float4*)(Bb + (size_t)r * HH + k0 + ac);
            float4 bh4, bl4;
            bh4.x = f2tf(u4.x); bl4.x = f2tf(u4.x - bh4.x);
            bh4.y = f2tf(u4.y); bl4.y = f2tf(u4.y - bh4.y);
            bh4.z = f2tf(u4.z); bl4.z = f2tf(u4.z - bh4.z);
            bh4.w = f2tf(u4.w); bl4.w = f2tf(u4.w - bh4.w);
            *(float4*)&Bh[r][ac] = bh4;
            *(float4*)&Bl[r][ac] = bl4;
        }
        __syncthreads();
#pragma unroll
        for (int kk = 0; kk < 4; kk++) {
            int kb = kk * 8;
            float ah[2][4], al[2][4];
#pragma unroll
            for (int mt = 0; mt < 2; mt++) {
                int m0 = wm * 32 + mt * 16;
                ah[mt][0] = Ah[m0 + g][kb + tig];
                ah[mt][1] = Ah[m0 + g + 8][kb + tig];
                ah[mt][2] = Ah[m0 + g][kb + tig + 4];
                ah[mt][3] = Ah[m0 + g + 8][kb + tig + 4];
                al[mt][0] = Al[m0 + g][kb + tig];
                al[mt][1] = Al[m0 + g + 8][kb + tig];
                al[mt][2] = Al[m0 + g][kb + tig + 4];
                al[mt][3] = Al[m0 + g + 8][kb + tig + 4];
            }
            float bh[4][2], bl[4][2];
#pragma unroll
            for (int nt = 0; nt < 4; nt++) {
                int nb = wn * 32 + nt * 8;
                bh[nt][0] = Bh[nb + g][kb + tig];
                bh[nt][1] = Bh[nb + g][kb + tig + 4];
                bl[nt][0] = Bl[nb + g][kb + tig];
                bl[nt][1] = Bl[nb + g][kb + tig + 4];
            }
#pragma unroll
            for (int mt = 0; mt < 2; mt++)
#pragma unroll
                for (int nt = 0; nt < 4; nt++) {
                    mma_tf32(acc[mt][nt], ah[mt], bh[nt]);
                    mma_tf32(acc[mt][nt], ah[mt], bl[nt]);
                    mma_tf32(acc[mt][nt], al[mt], bh[nt]);
                }
        }
        __syncthreads();
    }
#pragma unroll
    for (int mt = 0; mt < 2; mt++) {
#pragma unroll
        for (int nt = 0; nt < 4; nt++) {
            int col = t0 + wn * 32 + nt * 8 + 2 * tig;
            int row0 = p0 + wm * 32 + mt * 16 + g;
            *(float2*)&g_sim[b][row0][col]     = make_float2(acc[mt][nt][0], acc[mt][nt][1]);
            *(float2*)&g_sim[b][row0 + 8][col] = make_float2(acc[mt][nt][2], acc[mt][nt][3]);
            g_simT[b][col][row0]         = acc[mt][nt][0];
            g_simT[b][col + 1][row0]     = acc[mt][nt][1];
            g_simT[b][col][row0 + 8]     = acc[mt][nt][2];
            g_simT[b][col + 1][row0 + 8] = acc[mt][nt][3];
        }
    }
}

// ---------------- kernel 5: bidirectional softmax weights (row-chunked) ----------------
__global__ void __launch_bounds__(256) k_softmaxw() {
    int cx = blockIdx.x, dir = blockIdx.y, b = blockIdx.z;
    int tid = threadIdx.x, lane = tid & 31, w = tid >> 5;
    int s1 = g_s1[b], s2 = g_s2[b];
    __shared__ float acc8[8][512];

    if (dir == 0) {
        for (int i = tid; i < 8 * 512; i += 256) acc8[i >> 9][i & 511] = 0.f;
        __syncthreads();
        int np = s1 - 1;
        int len = (np + SCH - 1) / SCH;
        int lo = cx * len, hi = min(lo + len, np);
        for (int pi = lo + w; pi < hi; pi += 8) {
            int p = 1 + pi;
            const float* row = &g_sim[b][p][0];
            float sc[14];
            float m = -1e30f;
#pragma unroll
            for (int j = 0; j < 14; j++) {
                int tt = s1 + 1 + lane + j * 32;
                sc[j] = (tt < s2) ? row[tt] : -1e30f;
                m = fmaxf(m, sc[j]);
            }
#pragma unroll
            for (int o = 16; o; o >>= 1) m = fmaxf(m, __shfl_xor_sync(0xffffffffu, m, o));
            float s = 0.f;
#pragma unroll
            for (int j = 0; j < 14; j++) { sc[j] = __expf(sc[j] - m); s += sc[j]; }
#pragma unroll
            for (int o = 16; o; o >>= 1) s += __shfl_xor_sync(0xffffffffu, s, o);
            float inv = 1.f / s;
#pragma unroll
            for (int j = 0; j < 14; j++) {
                int tt = s1 + 1 + lane + j * 32;
                if (tt < s2) acc8[w][tt] += sc[j] * inv;
            }
        }
        __syncthreads();
        for (int i = tid; i < 512; i += 256) {
            float a = 0.f;
#pragma unroll
            for (int r = 0; r < 8; r++) a += acc8[r][i];
            g_whp[b][cx][i] = a;
        }
    } else {
        for (int i = tid; i < 8 * 256; i += 256) acc8[i >> 8][i & 255] = 0.f;
        __syncthreads();
        int nhy = s2 - s1 - 1;
        int len = (nhy + SCH - 1) / SCH;
        int lo = cx * len, hi = min(lo + len, nhy);
        for (int ti = lo + w; ti < hi; ti += 8) {
            int tt = s1 + 1 + ti;
            const float* rowT = &g_simT[b][tt][0];
            float sc[8];
            float m = -1e30f;
#pragma unroll
            for (int j = 0; j < 8; j++) {
                int p = 1 + lane + j * 32;
                sc[j] = (p < s1) ? rowT[p] : -1e30f;
                m = fmaxf(m, sc[j]);
            }
#pragma unroll
            for (int o = 16; o; o >>= 1) m = fmaxf(m, __shfl_xor_sync(0xffffffffu, m, o));
            float s = 0.f;
#pragma unroll
            for (int j = 0; j < 8; j++) { sc[j] = __expf(sc[j] - m); s += sc[j]; }
#pragma unroll
            for (int o = 16; o; o >>= 1) s += __shfl_xor_sync(0xffffffffu, s, o);
            float inv = 1.f / s;
#pragma unroll
            for (int j = 0; j < 8; j++) {
                int p = 1 + lane + j * 32;
                if (p < s1) acc8[w][p & 255] += sc[j] * inv;
            }
        }
        __syncthreads();
        if (tid < 256) {
            float a = 0.f;
#pragma unroll
            for (int r = 0; r < 8; r++) a += acc8[r][tid];
            g_wpp[b][cx][tid] = a;
        }
    }
}

// ---------------- kernel 6: fused hs streaming pass (1152 blocks) ----------------
__global__ void __launch_bounds__(128) k_stream(const float* __restrict__ hs) {
    int b = blockIdx.z, rch = blockIdx.y;
    int h = blockIdx.x * 128 + threadIdx.x;
    int s1 = g_s1[b], s2 = g_s2[b];
    __shared__ float w8[NHH][256];
    __shared__ float wh[SS];
    __shared__ float wp[256];
    int rt_lo = (s1 + 1) >> 5, rt_hi = (s2 - 1) >> 5;
    for (int i = threadIdx.x; i < NHH * 256; i += 128) {
        int hd = i >> 8, k = i & 255;
        float a = 0.f;
        for (int rt = rt_lo; rt <= rt_hi; rt++) a += g_wbp[b][hd][rt][k];
        w8[hd][k] = a;
    }
    for (int i = threadIdx.x; i < SS; i += 128) {
        float a = 0.f;
#pragma unroll
        for (int c = 0; c < SCH; c++) a += g_whp[b][c][i];
        wh[i] = a;
    }
    for (int i = threadIdx.x; i < 256; i += 128) {
        float a = 0.f;
#pragma unroll
        for (int c = 0; c < SCH; c++) a += g_wpp[b][c][i];
        wp[i] = a;
    }
    __syncthreads();

    int total = s2 + 1;
    int len = (total + RCH - 1) / RCH;
    int lo = rch * len;
    int hi = min(lo + len, total);

    const float* base = hs + (size_t)b * SS * HH + h;
    float sa = 0.f, mx = -1e9f, sp = 0.f, sh = 0.f;
    float a1 = 0.f, a2 = 0.f;
    float uacc[NHH] = {};

    int s = lo;
    for (; s + 3 < hi; s += 4) {
        float x[4];
#pragma unroll
        for (int j = 0; j < 4; j++) x[j] = base[(size_t)(s + j) * HH];
#pragma unroll
        for (int j = 0; j < 4; j++) {
            int ss = s + j;
            sa += x[j];
            mx = fmaxf(mx, x[j]);
            bool prem = (ss >= 1 && ss < s1);
            bool hyp  = (ss > s1 && ss < s2);
            if (prem) {
                sp += x[j];
                a2 += wp[ss] * x[j];
#pragma unroll
                for (int hd = 0; hd < NHH; hd++) uacc[hd] += w8[hd][ss] * x[j];
            }
            if (hyp) {
                sh += x[j];
                a1 += wh[ss] * x[j];
            }
        }
    }
    for (; s < hi; s++) {
        float x = base[(size_t)s * HH];
        sa += x; mx = fmaxf(mx, x);
        bool prem = (s >= 1 && s < s1);
        bool hyp  = (s > s1 && s < s2);
        if (prem) {
            sp += x;
            a2 += wp[s] * x;
#pragma unroll
            for (int hd = 0; hd < NHH; hd++) uacc[hd] += w8[hd][s] * x;
        }
        if (hyp) { sh += x; a1 += wh[s] * x; }
    }

    g_ps[b][rch][0][h] = sa;
    g_ps[b][rch][1][h] = mx;
    g_ps[b][rch][2][h] = sp;
    g_ps[b][rch][3][h] = sh;
#pragma unroll
    for (int hd = 0; hd < NHH; hd++) g_pu[b][rch][hd][h] = uacc[hd];
    g_pa[b][rch][0][h] = a1;
    g_pa[b][rch][1][h] = a2;
}

// ---------------- kernel 7: combine stream partials ----------------
__global__ void __launch_bounds__(128) k_finish(const float* __restrict__ hs) {
    int b = blockIdx.y;
    int h = blockIdx.x * 128 + threadIdx.x;
    int s1 = g_s1[b], s2 = g_s2[b];
    float sa = 0.f, mx = -1e9f, sp = 0.f, sh = 0.f, a1 = 0.f, a2 = 0.f;
    float u[NHH] = {};
#pragma unroll
    for (int r = 0; r < RCH; r++) {
        sa += g_ps[b][r][0][h];
        mx = fmaxf(mx, g_ps[b][r][1][h]);
        sp += g_ps[b][r][2][h];
        sh += g_ps[b][r][3][h];
        a1 += g_pa[b][r][0][h];
        a2 += g_pa[b][r][1][h];
#pragma unroll
        for (int hd = 0; hd < NHH; hd++) u[hd] += g_pu[b][r][hd][h];
    }
    float n_am = (float)(s2 + 1);
    float n_prem = (float)(s1 - 1);
    float n_hyp  = (float)(s2 - s1 - 1);
    float pooled = hs[(size_t)b * SS * HH + h];
    g_xfeat[b][h] = pooled + sa / n_am + mx;
    g_sdiff[b][h] = fabsf(sp / fmaxf(n_prem, 1e-9f) - sh / fmaxf(n_hyp, 1e-9f));
    float invh = 1.f / n_hyp;
#pragma unroll
    for (int hd = 0; hd < NHH; hd++) g_u[b][hd][h] = u[hd] * invh;
    g_al[b][h]      = a1 / n_prem;
    g_al[b][HH + h] = a2 / n_hyp;
}

// ---------------- kernel 8: merged per-batch heads (dual-accumulator GEMVs) ----------------
__global__ void __launch_bounds__(256) k_heads(
    const float* __restrict__ wv, const float* __restrict__ bv,
    const float* __restrict__ wo, const float* __restrict__ bo,
    const float* __restrict__ apw, const float* __restrict__ apb,
    const float* __restrict__ alw1, const float* __restrict__ alb1,
    const float* __restrict__ alw2, const float* __restrict__ alb2,
    const float* __restrict__ few1, const float* __restrict__ feb1,
    const float* __restrict__ feg, const float* __restrict__ febe,
    const float* __restrict__ few2, const float* __restrict__ feb2,
    const float* __restrict__ dpw, const float* __restrict__ dpb) {
    int task = blockIdx.x, b = blockIdx.y, t = threadIdx.x;
    __shared__ float sm[NHH * HH + 2 * HH];

    if (task == 0) {
        float* u  = sm;
        float* cp = sm + NHH * HH;
        float* cb = cp + HH;
        for (int i = t; i < NHH * HH; i += 256) u[i] = (&g_u[b][0][0])[i];
        __syncthreads();
        for (int o = t; o < 768; o += 256) {
            int ho = o / HDD;
            float acc0 = bv[o], acc1 = 0.f;
            const float* up = u + ho * HH;
            for (int j = 0; j < 768; j += 2) {
                acc0 += up[j] * wv[(size_t)j * 768 + o];
                acc1 += up[j + 1] * wv[(size_t)(j + 1) * 768 + o];
            }
            cp[o] = acc0 + acc1;
        }
        __syncthreads();
        for (int o = t; o < 768; o += 256) {
            float acc0 = bo[o], acc1 = 0.f;
            for (int j = 0; j < 768; j += 2) {
                acc0 += cp[j] * wo[(size_t)j * 768 + o];
                acc1 += cp[j + 1] * wo[(size_t)(j + 1) * 768 + o];
            }
            cb[o] = acc0 + acc1;
        }
        __syncthreads();
        for (int o = t; o < 128; o += 256) {
            float acc0 = apb[o], acc1 = 0.f;
            for (int j = 0; j < 768; j += 2) {
                acc0 += cb[j] * apw[j * 128 + o];
                acc1 += cb[j + 1] * apw[(j + 1) * 128 + o];
            }
            g_attnr[b][o] = telu_f(acc0 + acc1);
        }
    } else if (task == 1) {
        float* al = sm;
        float* h1 = sm + 1536;
        for (int i = t; i < 1536; i += 256) al[i] = g_al[b][i];
        __syncthreads();
        for (int o = t; o < 768; o += 256) {
            float acc0 = alb1[o], acc1 = 0.f;
            for (int j = 0; j < 1536; j += 2) {
                acc0 += al[j] * alw1[(size_t)j * 768 + o];
                acc1 += al[j + 1] * alw1[(size_t)(j + 1) * 768 + o];
            }
            h1[o] = acc0 + acc1;
        }
        __syncthreads();
        for (int o = t; o < 128; o += 256) {
            float acc0 = alb2[o], acc1 = 0.f;
            for (int j = 0; j < 768; j += 2) {
                acc0 += h1[j] * alw2[j * 128 + o];
                acc1 += h1[j + 1] * alw2[(j + 1) * 128 + o];
            }
            g_alignr[b][o] = telu_f(acc0 + acc1);
        }
    } else {
        float* x   = sm;
        float* h1  = sm + 768;
        float* red = sm + 1280;
        for (int i = t; i < 768; i += 256) x[i] = g_xfeat[b][i];
        __syncthreads();
        for (int o = t; o < 512; o += 256) {
            float acc0 = feb1[o], acc1 = 0.f;
            for (int j = 0; j < 768; j += 2) {
                acc0 += x[j] * few1[j * 512 + o];
                acc1 += x[j + 1] * few1[(j + 1) * 512 + o];
            }
            h1[o] = acc0 + acc1;
        }
        __syncthreads();
        red[t] = h1[t] + h1[t + 256]; __syncthreads();
        for (int o = 128; o; o >>= 1) { if (t < o) red[t] += red[t + o]; __syncthreads(); }
        float mean = red[0] * (1.f / 512.f);
        __syncthreads();
        float d0 = h1[t] - mean, d1 = h1[t + 256] - mean;
        red[t] = d0 * d0 + d1 * d1; __syncthreads();
        for (int o = 128; o; o >>= 1) { if (t < o) red[t] += red[t + o]; __syncthreads(); }
        float rstd = rsqrtf(red[0] * (1.f / 512.f) + 1e-5f);
        __syncthreads();
        h1[t]       = (h1[t] - mean) * rstd * feg[t] + febe[t];
        h1[t + 256] = (h1[t + 256] - mean) * rstd * feg[t + 256] + febe[t + 256];
        __syncthreads();
        if (t < 128) {
            float acc0 = feb2[t], acc1 = 0.f;
            for (int j = 0; j < 512; j += 2) {
                acc0 += h1[j] * few2[j * 128 + t];
                acc1 += h1[j + 1] * few2[(j + 1) * 128 + t];
            }
            g_feat[b][t] = telu_f(acc0 + acc1);
        }
        __syncthreads();
        for (int i = t; i < 768; i += 256) x[i] = g_sdiff[b][i];
        __syncthreads();
        if (t < 128) {
            float acc0 = dpb[t], acc1 = 0.f;
            for (int j = 0; j < 768; j += 2) {
                acc0 += x[j] * dpw[j * 128 + t];
                acc1 += x[j + 1] * dpw[(j + 1) * 128 + t];
            }
            g_diff[b][t] = telu_f(acc0 + acc1);
        }
    }
}

// ---------------- kernel 9: classifier ----------------
__global__ void __launch_bounds__(128) k_cls(const float* __restrict__ w1, const float* __restrict__ b1,
                                             const float* __restrict__ w2, const float* __restrict__ b2,
                                             float* __restrict__ out) {
    int b = blockIdx.x, t = threadIdx.x;
    __shared__ float comb[512];
    __shared__ float hh[64];
    comb[t] = g_feat[b][t];
    comb[128 + t] = g_diff[b][t];
    comb[256 + t] = g_attnr[b][t];
    comb[384 + t] = g_alignr[b][t];
    __syncthreads();
    if (t < 64) {
        float acc0 = b1[t], acc1 = 0.f;
        for (int j = 0; j < 512; j += 2) {
            acc0 += comb[j] * w1[j * 64 + t];
            acc1 += comb[j + 1] * w1[(j + 1) * 64 + t];
        }
        hh[t] = telu_f(acc0 + acc1);
    }
    __syncthreads();
    if (t < 3) {
        float acc = b2[t];
        for (int j = 0; j < 64; j++) acc += hh[j] * w2[j * 3 + t];
        out[b * 3 + t] = acc;
    }
}

// ---------------- launcher ----------------
extern "C" void kernel_launch(void* const* d_in, const int* in_sizes, int n_in,
                              void* d_out, int out_size) {
    (void)in_sizes; (void)n_in; (void)out_size;
    const float* hs   = (const float*)d_in[0];
    const int*   ids  = (const int*)d_in[1];
    const float* few1 = (const float*)d_in[3];
    const float* feb1 = (const float*)d_in[4];
    const float* feg  = (const float*)d_in[5];
    const float* febe = (const float*)d_in[6];
    const float* few2 = (const float*)d_in[7];
    const float* feb2 = (const float*)d_in[8];
    const float* alw1 = (const float*)d_in[9];
    const float* alb1 = (const float*)d_in[10];
    const float* alw2 = (const float*)d_in[11];
    const float* alb2 = (const float*)d_in[12];
    const float* wq   = (const float*)d_in[13];
    const float* bq   = (const float*)d_in[14];
    const float* wk   = (const float*)d_in[15];
    const float* bk   = (const float*)d_in[16];
    const float* wv   = (const float*)d_in[17];
    const float* bv   = (const float*)d_in[18];
    const float* wo   = (const float*)d_in[19];
    const float* bo   = (const float*)d_in[20];
    const float* dpw  = (const float*)d_in[21];
    const float* dpb  = (const float*)d_in[22];
    const float* apw  = (const float*)d_in[23];
    const float* apb  = (const float*)d_in[24];
    const float* clw1 = (const float*)d_in[25];
    const float* clb1 = (const float*)d_in[26];
    const float* clw2 = (const float*)d_in[27];
    const float* clb2 = (const float*)d_in[28];
    float* out = (float*)d_out;

    k_sep<<<BB, 128>>>(ids);                                      // 1
    k_gemm_qk<<<dim3(6, 4, BB * 2), 256>>>(hs, wq, bq, wk, bk);   // 2
    k_score_fused<<<dim3(16, NHH, BB), 256>>>();                  // 3
    k_gemm_sim<<<dim3(4, 4, BB), 256>>>(hs);                      // 4 <- profiled slot
    k_softmaxw<<<dim3(SCH, 2, BB), 256>>>();                      // 5
    k_stream<<<dim3(6, RCH, BB), 128>>>(hs);                      // 6
    k_finish<<<dim3(6, BB), 128>>>(hs);                           // 7
    k_heads<<<dim3(3, BB), 256>>>(wv, bv, wo, bo, apw, apb,
                                  alw1, alb1, alw2, alb2,
                                  few1, feb1, feg, febe, few2, feb2,
                                  dpw, dpb);                      // 8
    k_cls<<<BB, 128>>>(clw1, clb1, clw2, clb2, out);              // 9
}

// round 17
// speedup vs baseline: 1.1625x; 1.1625x over previous
#include <cuda_runtime.h>
#include <math.h>
#include <stdint.h>

#define BB 32
#define SS 512
#define HH 768
#define NHH 8
#define HDD 96
#define SEPTOK 102
#define RCH 6   // row chunks for streaming pass
#define SCH 4   // row chunks for softmaxw

// ---------------- scratch ----------------
__device__ int   g_s1[BB], g_s2[BB];
__device__ float g_xfeat[BB][HH];
__device__ float g_sdiff[BB][HH];
__device__ float g_Q[BB][SS][HH];
__device__ float g_K[BB][SS][HH];
__device__ float g_wbp[BB][NHH][16][256];
__device__ float g_whp[BB][SCH][SS];
__device__ float g_wpp[BB][SCH][256];
__device__ float g_u[BB][NHH][HH];
__device__ float g_sim[BB][256][SS];
__device__ float g_simT[BB][SS][256];
__device__ float g_al[BB][2 * HH];
__device__ float g_ps[BB][RCH][4][HH];
__device__ float g_pu[BB][RCH][NHH][HH];
__device__ float g_pa[BB][RCH][2][HH];
__device__ float g_feat[BB][128];
__device__ float g_diff[BB][128];
__device__ float g_attnr[BB][128];
__device__ float g_alignr[BB][128];

__device__ __forceinline__ float telu_f(float x) {
    return x * tanhf(__expf(x));
}

__device__ __forceinline__ float f2tf(float x) {
    uint32_t u;
    asm("cvt.rna.tf32.f32 %0, %1;" : "=r"(u) : "f"(x));
    return __uint_as_float(u);
}

__device__ __forceinline__ void mma_tf32(float* d, const float* a, const float* bfr) {
    asm volatile(
        "mma.sync.aligned.m16n8k8.row.col.f32.tf32.tf32.f32 "
        "{%0,%1,%2,%3}, {%4,%5,%6,%7}, {%8,%9}, {%0,%1,%2,%3};"
        : "+f"(d[0]), "+f"(d[1]), "+f"(d[2]), "+f"(d[3])
        : "r"(__float_as_uint(a[0])), "r"(__float_as_uint(a[1])),
          "r"(__float_as_uint(a[2])), "r"(__float_as_uint(a[3])),
          "r"(__float_as_uint(bfr[0])), "r"(__float_as_uint(bfr[1])));
}

__device__ __forceinline__ void cp16(void* smem_dst, const void* gsrc) {
    uint32_t d = (uint32_t)__cvta_generic_to_shared(smem_dst);
    asm volatile("cp.async.cg.shared.global [%0], [%1], 16;" :: "r"(d), "l"(gsrc));
}

// ---------------- kernel 1: find SEP positions ----------------
__global__ void k_sep(const int* __restrict__ ids) {
    int b = blockIdx.x, t = threadIdx.x;
    __shared__ int smn[128], smx[128];
    int mn = SS, mx = -1;
    for (int s = t; s < SS; s += 128) {
        int v = ids[b * SS + s];
        if (v == SEPTOK) { if (s < mn) mn = s; if (s > mx) mx = s; }
    }
    smn[t] = mn; smx[t] = mx; __syncthreads();
    for (int o = 64; o; o >>= 1) {
        if (t < o) { smn[t] = min(smn[t], smn[t + o]); smx[t] = max(smx[t], smx[t + o]); }
        __syncthreads();
    }
    if (t == 0) { g_s1[b] = smn[0]; g_s2[b] = smx[0]; }
}

// ---------------- kernel 2: masked Q/K projection, 128x128 tile, 256 thr, mt4/nt4 ----------------
__global__ void __launch_bounds__(256) k_gemm_qk(
    const float* __restrict__ hs,
    const float* __restrict__ wq, const float* __restrict__ bq,
    const float* __restrict__ wk, const float* __restrict__ bk) {
    int z = blockIdx.z;
    int mat = z & 1, b = z >> 1;
    int s1 = g_s1[b], s2 = g_s2[b];
    int r0 = blockIdx.y * 128;
    int lo = mat ? 1 : (s1 + 1);
    int hi = mat ? (s1 - 1) : (s2 - 1);
    if (r0 > hi || r0 + 127 < lo) return;
    const float* W    = mat ? wk : wq;
    const float* bias = mat ? bk : bq;
    float* out        = mat ? &g_K[b][0][0] : &g_Q[b][0][0];
    float oscale      = mat ? 1.f : 0.10206207261596575f;
    int n0 = blockIdx.x * 128;

    __shared__ __align__(16) float As[2][128][36];
    __shared__ __align__(16) float Bs[2][32][132];

    int tid = threadIdx.x;
    int lane = tid & 31, warp = tid >> 5;
    int g = lane >> 2, tig = lane & 3;
    int wm = warp >> 2, wn = warp & 3;

    float acc[4][4][4] = {};

    int ar = tid >> 3, ac = (tid & 7) * 4;
    int bkr = tid >> 4, bnc = (tid & 15) * 8;

    const float* Ab = hs + ((size_t)b * SS + r0) * HH;

    const int NCH = HH / 32;
#define QK_LOAD(st, k0)                                                              \
    do {                                                                             \
        cp16(&As[st][ar][ac],      Ab + (size_t)ar * HH + (k0) + ac);                \
        cp16(&As[st][ar + 32][ac], Ab + (size_t)(ar + 32) * HH + (k0) + ac);         \
        cp16(&As[st][ar + 64][ac], Ab + (size_t)(ar + 64) * HH + (k0) + ac);         \
        cp16(&As[st][ar + 96][ac], Ab + (size_t)(ar + 96) * HH + (k0) + ac);         \
        cp16(&Bs[st][bkr][bnc],          W + (size_t)((k0) + bkr) * HH + n0 + bnc);      \
        cp16(&Bs[st][bkr][bnc + 4],      W + (size_t)((k0) + bkr) * HH + n0 + bnc + 4);  \
        cp16(&Bs[st][bkr + 16][bnc],     W + (size_t)((k0) + bkr + 16) * HH + n0 + bnc); \
        cp16(&Bs[st][bkr + 16][bnc + 4], W + (size_t)((k0) + bkr + 16) * HH + n0 + bnc + 4); \
        asm volatile("cp.async.commit_group;");                                      \
    } while (0)

    QK_LOAD(0, 0);
    for (int chunk = 0; chunk < NCH; chunk++) {
        int st = chunk & 1;
        if (chunk + 1 < NCH) {
            QK_LOAD(st ^ 1, (chunk + 1) * 32);
            asm volatile("cp.async.wait_group 1;");
        } else {
            asm volatile("cp.async.wait_group 0;");
        }
        __syncthreads();
#pragma unroll
        for (int kk = 0; kk < 4; kk++) {
            int kb = kk * 8;
            float a[4][4];
#pragma unroll
            for (int mt = 0; mt < 4; mt++) {
                int m0 = wm * 64 + mt * 16;
                a[mt][0] = As[st][m0 + g][kb + tig];
                a[mt][1] = As[st][m0 + g + 8][kb + tig];
                a[mt][2] = As[st][m0 + g][kb + tig + 4];
                a[mt][3] = As[st][m0 + g + 8][kb + tig + 4];
            }
            float bf[4][2];
#pragma unroll
            for (int nt = 0; nt < 4; nt++) {
                int nb = wn * 32 + nt * 8;
                bf[nt][0] = Bs[st][kb + tig][nb + g];
                bf[nt][1] = Bs[st][kb + tig + 4][nb + g];
            }
#pragma unroll
            for (int mt = 0; mt < 4; mt++)
#pragma unroll
                for (int nt = 0; nt < 4; nt++)
                    mma_tf32(acc[mt][nt], a[mt], bf[nt]);
        }
        __syncthreads();
    }
#undef QK_LOAD
#pragma unroll
    for (int mt = 0; mt < 4; mt++) {
#pragma unroll
        for (int nt = 0; nt < 4; nt++) {
            int col = n0 + wn * 32 + nt * 8 + 2 * tig;
            float b0 = bias[col], b1 = bias[col + 1];
            int row0 = r0 + wm * 64 + mt * 16 + g;
            *(float2*)&out[(size_t)row0 * HH + col] =
                make_float2((acc[mt][nt][0] + b0) * oscale, (acc[mt][nt][1] + b1) * oscale);
            *(float2*)&out[(size_t)(row0 + 8) * HH + col] =
                make_float2((acc[mt][nt][2] + b0) * oscale, (acc[mt][nt][3] + b1) * oscale);
        }
    }
}

// ---------------- kernel 3: fused scores + row softmax -> wbar partials ----------------
__global__ void __launch_bounds__(256) k_score_fused() {
    int rt = blockIdx.x, h = blockIdx.y, b = blockIdx.z;
    int s1 = g_s1[b], s2 = g_s2[b];
    int r0 = rt * 32;
    if (r0 > s2 - 1 || r0 + 31 < s1 + 1) return;

    __shared__ float Aq[32][100];
    __shared__ float Bs[64][36];
    __shared__ float sc[32][260];
    __shared__ float wb[8][256];

    int tid = threadIdx.x;
    int lane = tid & 31, warp = tid >> 5;
    int g = lane >> 2, tig = lane & 3;
    int wm = warp >> 2, wn = warp & 3;

    {
        int row = tid >> 3;
        int c0 = (tid & 7) * 12;
#pragma unroll
        for (int i = 0; i < 3; i++) {
            float4 v = *(const float4*)(&g_Q[b][r0 + row][h * HDD + c0 + i * 4]);
            *(float4*)&Aq[row][c0 + i * 4] = v;
        }
    }
    for (int i = tid; i < 8 * 256; i += 256) wb[i >> 8][i & 255] = 0.f;

    int tcount = (s1 + 63) >> 6;
    int ar = tid >> 3, ac = (tid & 7) * 4;

    for (int tt = 0; tt < tcount; tt++) {
        int t0 = tt * 64;
        float acc[2][4] = {};
#pragma unroll
        for (int k0 = 0; k0 < HDD; k0 += 32) {
            __syncthreads();
#pragma unroll
            for (int rr = 0; rr < 2; rr++) {
                int r = ar + rr * 32;
                float4 v = *(const float4*)(&g_K[b][t0 + r][h * HDD + k0 + ac]);
                *(float4*)&Bs[r][ac] = v;
            }
            __syncthreads();
#pragma unroll
            for (int kk = 0; kk < 4; kk++) {
                int kb = kk * 8;
                int m0 = wm * 16;
                float a[4];
                a[0] = Aq[m0 + g][k0 + kb + tig];
                a[1] = Aq[m0 + g + 8][k0 + kb + tig];
                a[2] = Aq[m0 + g][k0 + kb + tig + 4];
                a[3] = Aq[m0 + g + 8][k0 + kb + tig + 4];
                float bf[2][2];
#pragma unroll
                for (int nt = 0; nt < 2; nt++) {
                    int nb = wn * 16 + nt * 8;
                    bf[nt][0] = Bs[nb + g][kb + tig];
                    bf[nt][1] = Bs[nb + g][kb + tig + 4];
                }
#pragma unroll
                for (int nt = 0; nt < 2; nt++)
                    mma_tf32(acc[nt], a, bf[nt]);
            }
        }
#pragma unroll
        for (int nt = 0; nt < 2; nt++) {
            int col = t0 + wn * 16 + nt * 8 + 2 * tig;
            int row0 = wm * 16 + g;
            *(float2*)&sc[row0][col]     = make_float2(acc[nt][0], acc[nt][1]);
            *(float2*)&sc[row0 + 8][col] = make_float2(acc[nt][2], acc[nt][3]);
        }
    }
    __syncthreads();

    int lo = max(r0, s1 + 1), hi = min(r0 + 32, s2);
    for (int s = lo + warp; s < hi; s += 8) {
        const float* row = &sc[s - r0][0];
        float scv[8];
        float m = -1e30f;
#pragma unroll
        for (int j = 0; j < 8; j++) {
            int k = lane + j * 32;
            scv[j] = (k >= 1 && k < s1) ? row[k] : -1e30f;
            m = fmaxf(m, scv[j]);
        }
#pragma unroll
        for (int o = 16; o; o >>= 1) m = fmaxf(m, __shfl_xor_sync(0xffffffffu, m, o));
        float sum = 0.f;
#pragma unroll
        for (int j = 0; j < 8; j++) { scv[j] = __expf(scv[j] - m); sum += scv[j]; }
#pragma unroll
        for (int o = 16; o; o >>= 1) sum += __shfl_xor_sync(0xffffffffu, sum, o);
        float inv = 1.f / sum;
#pragma unroll
        for (int j = 0; j < 8; j++) {
            int k = lane + j * 32;
            if (k >= 1 && k < s1) wb[warp][k] += scv[j] * inv;
        }
        __syncwarp();
    }
    __syncthreads();
    if (tid < 256) {
        float a = 0.f;
#pragma unroll
        for (int r = 0; r < 8; r++) a += wb[r][tid];
        g_wbp[b][h][rt][tid] = a;
    }
}

// ---------------- kernel 4: sim 64x64 tile, mt2/nt2, split-tf32 (profiled slot) ----------------
__global__ void __launch_bounds__(256) k_gemm_sim(const float* __restrict__ hs) {
    int b = blockIdx.z;
    int s1 = g_s1[b], s2 = g_s2[b];
    int p0 = blockIdx.y * 64, t0 = blockIdx.x * 64;
    if (p0 > s1 - 1) return;
    if (t0 > s2 - 1 || t0 + 63 < s1 + 1) return;

    __shared__ float Ah[64][36], Al[64][36];
    __shared__ float Bh[64][36], Bl[64][36];

    int tid = threadIdx.x;
    int lane = tid & 31, warp = tid >> 5;
    int g = lane >> 2, tig = lane & 3;
    int wm = warp >> 2, wn = warp & 3;

    float acc[2][2][4] = {};

    int ar = tid >> 3, ac = (tid & 7) * 4;
    const float* Ab = hs + ((size_t)b * SS + p0) * HH;
    const float* Bb = hs + ((size_t)b * SS + t0) * HH;

    for (int k0 = 0; k0 < HH; k0 += 32) {
#pragma unroll
        for (int rr = 0; rr < 2; rr++) {
            int r = ar + rr * 32;
            float4 v = *(const float4*)(Ab + (size_t)r * HH + k0 + ac);
            float4 h4, l4;
            h4.x = f2tf(v.x); l4.x = f2tf(v.x - h4.x);
            h4.y = f2tf(v.y); l4.y = f2tf(v.y - h4.y);
            h4.z = f2tf(v.z); l4.z = f2tf(v.z - h4.z);
            h4.w = f2tf(v.w); l4.w = f2tf(v.w - h4.w);
            *(float4*)&Ah[r][ac] = h4;
            *(float4*)&Al[r][ac] = l4;
            float4 u4 = *(const float4*)(Bb + (size_t)r * HH + k0 + ac);
            float4 bh4, bl4;
            bh4.x = f2tf(u4.x); bl4.x = f2tf(u4.x - bh4.x);
            bh4.y = f2tf(u4.y); bl4.y = f2tf(u4.y - bh4.y);
            bh4.z = f2tf(u4.z); bl4.z = f2tf(u4.z - bh4.z);
            bh4.w = f2tf(u4.w); bl4.w = f2tf(u4.w - bh4.w);
            *(float4*)&Bh[r][ac] = bh4;
            *(float4*)&Bl[r][ac] = bl4;
        }
        __syncthreads();
#pragma unroll
        for (int kk = 0; kk < 4; kk++) {
            int kb = kk * 8;
            float ah[2][4], al[2][4];
#pragma unroll
            for (int mt = 0; mt < 2; mt++) {
                int m0 = wm * 32 + mt * 16;
                ah[mt][0] = Ah[m0 + g][kb + tig];
                ah[mt][1] = Ah[m0 + g + 8][kb + tig];
                ah[mt][2] = Ah[m0 + g][kb + tig + 4];
                ah[mt][3] = Ah[m0 + g + 8][kb + tig + 4];
                al[mt][0] = Al[m0 + g][kb + tig];
                al[mt][1] = Al[m0 + g + 8][kb + tig];
                al[mt][2] = Al[m0 + g][kb + tig + 4];
                al[mt][3] = Al[m0 + g + 8][kb + tig + 4];
            }
            float bh[2][2], bl[2][2];
#pragma unroll
            for (int nt = 0; nt < 2; nt++) {
                int nb = wn * 16 + nt * 8;
                bh[nt][0] = Bh[nb + g][kb + tig];
                bh[nt][1] = Bh[nb + g][kb + tig + 4];
                bl[nt][0] = Bl[nb + g][kb + tig];
                bl[nt][1] = Bl[nb + g][kb + tig + 4];
            }
#pragma unroll
            for (int mt = 0; mt < 2; mt++)
#pragma unroll
                for (int nt = 0; nt < 2; nt++) {
                    mma_tf32(acc[mt][nt], ah[mt], bh[nt]);
                    mma_tf32(acc[mt][nt], ah[mt], bl[nt]);
                    mma_tf32(acc[mt][nt], al[mt], bh[nt]);
                }
        }
        __syncthreads();
    }
#pragma unroll
    for (int mt = 0; mt < 2; mt++) {
#pragma unroll
        for (int nt = 0; nt < 2; nt++) {
            int col = t0 + wn * 16 + nt * 8 + 2 * tig;
            int row0 = p0 + wm * 32 + mt * 16 + g;
            *(float2*)&g_sim[b][row0][col]     = make_float2(acc[mt][nt][0], acc[mt][nt][1]);
            *(float2*)&g_sim[b][row0 + 8][col] = make_float2(acc[mt][nt][2], acc[mt][nt][3]);
            g_simT[b][col][row0]         = acc[mt][nt][0];
            g_simT[b][col + 1][row0]     = acc[mt][nt][1];
            g_simT[b][col][row0 + 8]     = acc[mt][nt][2];
            g_simT[b][col + 1][row0 + 8] = acc[mt][nt][3];
        }
    }
}

// ---------------- kernel 5: bidirectional softmax weights (row-chunked) ----------------
__global__ void __launch_bounds__(256) k_softmaxw() {
    int cx = blockIdx.x, dir = blockIdx.y, b = blockIdx.z;
    int tid = threadIdx.x, lane = tid & 31, w = tid >> 5;
    int s1 = g_s1[b], s2 = g_s2[b];
    __shared__ float acc8[8][512];

    if (dir == 0) {
        for (int i = tid; i < 8 * 512; i += 256) acc8[i >> 9][i & 511] = 0.f;
        __syncthreads();
        int np = s1 - 1;
        int len = (np + SCH - 1) / SCH;
        int lo = cx * len, hi = min(lo + len, np);
        for (int pi = lo + w; pi < hi; pi += 8) {
            int p = 1 + pi;
            const float* row = &g_sim[b][p][0];
            float sc[14];
            float m = -1e30f;
#pragma unroll
            for (int j = 0; j < 14; j++) {
                int tt = s1 + 1 + lane + j * 32;
                sc[j] = (tt < s2) ? row[tt] : -1e30f;
                m = fmaxf(m, sc[j]);
            }
#pragma unroll
            for (int o = 16; o; o >>= 1) m = fmaxf(m, __shfl_xor_sync(0xffffffffu, m, o));
            float s = 0.f;
#pragma unroll
            for (int j = 0; j < 14; j++) { sc[j] = __expf(sc[j] - m); s += sc[j]; }
#pragma unroll
            for (int o = 16; o; o >>= 1) s += __shfl_xor_sync(0xffffffffu, s, o);
            float inv = 1.f / s;
#pragma unroll
            for (int j = 0; j < 14; j++) {
                int tt = s1 + 1 + lane + j * 32;
                if (tt < s2) acc8[w][tt] += sc[j] * inv;
            }
        }
        __syncthreads();
        for (int i = tid; i < 512; i += 256) {
            float a = 0.f;
#pragma unroll
            for (int r = 0; r < 8; r++) a += acc8[r][i];
            g_whp[b][cx][i] = a;
        }
    } else {
        for (int i = tid; i < 8 * 256; i += 256) acc8[i >> 8][i & 255] = 0.f;
        __syncthreads();
        int nhy = s2 - s1 - 1;
        int len = (nhy + SCH - 1) / SCH;
        int lo = cx * len, hi = min(lo + len, nhy);
        for (int ti = lo + w; ti < hi; ti += 8) {
            int tt = s1 + 1 + ti;
            const float* rowT = &g_simT[b][tt][0];
            float sc[8];
            float m = -1e30f;
#pragma unroll
            for (int j = 0; j < 8; j++) {
                int p = 1 + lane + j * 32;
                sc[j] = (p < s1) ? rowT[p] : -1e30f;
                m = fmaxf(m, sc[j]);
            }
#pragma unroll
            for (int o = 16; o; o >>= 1) m = fmaxf(m, __shfl_xor_sync(0xffffffffu, m, o));
            float s = 0.f;
#pragma unroll
            for (int j = 0; j < 8; j++) { sc[j] = __expf(sc[j] - m); s += sc[j]; }
#pragma unroll
            for (int o = 16; o; o >>= 1) s += __shfl_xor_sync(0xffffffffu, s, o);
            float inv = 1.f / s;
#pragma unroll
            for (int j = 0; j < 8; j++) {
                int p = 1 + lane + j * 32;
                if (p < s1) acc8[w][p & 255] += sc[j] * inv;
            }
        }
        __syncthreads();
        if (tid < 256) {
            float a = 0.f;
#pragma unroll
            for (int r = 0; r < 8; r++) a += acc8[r][tid];
            g_wpp[b][cx][tid] = a;
        }
    }
}

// ---------------- kernel 6: fused hs streaming pass (1152 blocks) ----------------
__global__ void __launch_bounds__(128) k_stream(const float* __restrict__ hs) {
    int b = blockIdx.z, rch = blockIdx.y;
    int h = blockIdx.x * 128 + threadIdx.x;
    int s1 = g_s1[b], s2 = g_s2[b];
    __shared__ float w8[NHH][256];
    __shared__ float wh[SS];
    __shared__ float wp[256];
    int rt_lo = (s1 + 1) >> 5, rt_hi = (s2 - 1) >> 5;
    for (int i = threadIdx.x; i < NHH * 256; i += 128) {
        int hd = i >> 8, k = i & 255;
        float a = 0.f;
        for (int rt = rt_lo; rt <= rt_hi; rt++) a += g_wbp[b][hd][rt][k];
        w8[hd][k] = a;
    }
    for (int i = threadIdx.x; i < SS; i += 128) {
        float a = 0.f;
#pragma unroll
        for (int c = 0; c < SCH; c++) a += g_whp[b][c][i];
        wh[i] = a;
    }
    for (int i = threadIdx.x; i < 256; i += 128) {
        float a = 0.f;
#pragma unroll
        for (int c = 0; c < SCH; c++) a += g_wpp[b][c][i];
        wp[i] = a;
    }
    __syncthreads();

    int total = s2 + 1;
    int len = (total + RCH - 1) / RCH;
    int lo = rch * len;
    int hi = min(lo + len, total);

    const float* base = hs + (size_t)b * SS * HH + h;
    float sa = 0.f, mx = -1e9f, sp = 0.f, sh = 0.f;
    float a1 = 0.f, a2 = 0.f;
    float uacc[NHH] = {};

    int s = lo;
    for (; s + 3 < hi; s += 4) {
        float x[4];
#pragma unroll
        for (int j = 0; j < 4; j++) x[j] = base[(size_t)(s + j) * HH];
#pragma unroll
        for (int j = 0; j < 4; j++) {
            int ss = s + j;
            sa += x[j];
            mx = fmaxf(mx, x[j]);
            bool prem = (ss >= 1 && ss < s1);
            bool hyp  = (ss > s1 && ss < s2);
            if (prem) {
                sp += x[j];
                a2 += wp[ss] * x[j];
#pragma unroll
                for (int hd = 0; hd < NHH; hd++) uacc[hd] += w8[hd][ss] * x[j];
            }
            if (hyp) {
                sh += x[j];
                a1 += wh[ss] * x[j];
            }
        }
    }
    for (; s < hi; s++) {
        float x = base[(size_t)s * HH];
        sa += x; mx = fmaxf(mx, x);
        bool prem = (s >= 1 && s < s1);
        bool hyp  = (s > s1 && s < s2);
        if (prem) {
            sp += x;
            a2 += wp[s] * x;
#pragma unroll
            for (int hd = 0; hd < NHH; hd++) uacc[hd] += w8[hd][s] * x;
        }
        if (hyp) { sh += x; a1 += wh[s] * x; }
    }

    g_ps[b][rch][0][h] = sa;
    g_ps[b][rch][1][h] = mx;
    g_ps[b][rch][2][h] = sp;
    g_ps[b][rch][3][h] = sh;
#pragma unroll
    for (int hd = 0; hd < NHH; hd++) g_pu[b][rch][hd][h] = uacc[hd];
    g_pa[b][rch][0][h] = a1;
    g_pa[b][rch][1][h] = a2;
}

// ---------------- kernel 7: combine stream partials ----------------
__global__ void __launch_bounds__(128) k_finish(const float* __restrict__ hs) {
    int b = blockIdx.y;
    int h = blockIdx.x * 128 + threadIdx.x;
    int s1 = g_s1[b], s2 = g_s2[b];
    float sa = 0.f, mx = -1e9f, sp = 0.f, sh = 0.f, a1 = 0.f, a2 = 0.f;
    float u[NHH] = {};
#pragma unroll
    for (int r = 0; r < RCH; r++) {
        sa += g_ps[b][r][0][h];
        mx = fmaxf(mx, g_ps[b][r][1][h]);
        sp += g_ps[b][r][2][h];
        sh += g_ps[b][r][3][h];
        a1 += g_pa[b][r][0][h];
        a2 += g_pa[b][r][1][h];
#pragma unroll
        for (int hd = 0; hd < NHH; hd++) u[hd] += g_pu[b][r][hd][h];
    }
    float n_am = (float)(s2 + 1);
    float n_prem = (float)(s1 - 1);
    float n_hyp  = (float)(s2 - s1 - 1);
    float pooled = hs[(size_t)b * SS * HH + h];
    g_xfeat[b][h] = pooled + sa / n_am + mx;
    g_sdiff[b][h] = fabsf(sp / fmaxf(n_prem, 1e-9f) - sh / fmaxf(n_hyp, 1e-9f));
    float invh = 1.f / n_hyp;
#pragma unroll
    for (int hd = 0; hd < NHH; hd++) g_u[b][hd][h] = u[hd] * invh;
    g_al[b][h]      = a1 / n_prem;
    g_al[b][HH + h] = a2 / n_hyp;
}

// ---------------- kernel 8: merged per-batch heads (attnrep | alignrep | feat) ----------------
__global__ void __launch_bounds__(256) k_heads(
    const float* __restrict__ wv, const float* __restrict__ bv,
    const float* __restrict__ wo, const float* __restrict__ bo,
    const float* __restrict__ apw, const float* __restrict__ apb,
    const float* __restrict__ alw1, const float* __restrict__ alb1,
    const float* __restrict__ alw2, const float* __restrict__ alb2,
    const float* __restrict__ few1, const float* __restrict__ feb1,
    const float* __restrict__ feg, const float* __restrict__ febe,
    const float* __restrict__ few2, const float* __restrict__ feb2,
    const float* __restrict__ dpw, const float* __restrict__ dpb) {
    int task = blockIdx.x, b = blockIdx.y, t = threadIdx.x;
    __shared__ float sm[NHH * HH + 2 * HH];

    if (task == 0) {
        float* u  = sm;
        float* cp = sm + NHH * HH;
        float* cb = cp + HH;
        for (int i = t; i < NHH * HH; i += 256) u[i] = (&g_u[b][0][0])[i];
        __syncthreads();
        for (int o = t; o < 768; o += 256) {
            int ho = o / HDD;
            float acc = bv[o];
            const float* up = u + ho * HH;
            for (int j = 0; j < 768; j++) acc += up[j] * wv[(size_t)j * 768 + o];
            cp[o] = acc;
        }
        __syncthreads();
        for (int o = t; o < 768; o += 256) {
            float acc = bo[o];
            for (int j = 0; j < 768; j++) acc += cp[j] * wo[(size_t)j * 768 + o];
            cb[o] = acc;
        }
        __syncthreads();
        for (int o = t; o < 128; o += 256) {
            float acc = apb[o];
            for (int j = 0; j < 768; j++) acc += cb[j] * apw[j * 128 + o];
            g_attnr[b][o] = telu_f(acc);
        }
    } else if (task == 1) {
        float* al = sm;
        float* h1 = sm + 1536;
        for (int i = t; i < 1536; i += 256) al[i] = g_al[b][i];
        __syncthreads();
        for (int o = t; o < 768; o += 256) {
            float acc = alb1[o];
            for (int j = 0; j < 1536; j++) acc += al[j] * alw1[(size_t)j * 768 + o];
            h1[o] = acc;
        }
        __syncthreads();
        for (int o = t; o < 128; o += 256) {
            float acc = alb2[o];
            for (int j = 0; j < 768; j++) acc += h1[j] * alw2[j * 128 + o];
            g_alignr[b][o] = telu_f(acc);
        }
    } else {
        float* x   = sm;
        float* h1  = sm + 768;
        float* red = sm + 1280;
        for (int i = t; i < 768; i += 256) x[i] = g_xfeat[b][i];
        __syncthreads();
        for (int o = t; o < 512; o += 256) {
            float acc = feb1[o];
            for (int j = 0; j < 768; j++) acc += x[j] * few1[j * 512 + o];
            h1[o] = acc;
        }
        __syncthreads();
        red[t] = h1[t] + h1[t + 256]; __syncthreads();
        for (int o = 128; o; o >>= 1) { if (t < o) red[t] += red[t + o]; __syncthreads(); }
        float mean = red[0] * (1.f / 512.f);
        __syncthreads();
        float d0 = h1[t] - mean, d1 = h1[t + 256] - mean;
        red[t] = d0 * d0 + d1 * d1; __syncthreads();
        for (int o = 128; o; o >>= 1) { if (t < o) red[t] += red[t + o]; __syncthreads(); }
        float rstd = rsqrtf(red[0] * (1.f / 512.f) + 1e-5f);
        __syncthreads();
        h1[t]       = (h1[t] - mean) * rstd * feg[t] + febe[t];
        h1[t + 256] = (h1[t + 256] - mean) * rstd * feg[t + 256] + febe[t + 256];
        __syncthreads();
        if (t < 128) {
            float acc = feb2[t];
            for (int j = 0; j < 512; j++) acc += h1[j] * few2[j * 128 + t];
            g_feat[b][t] = telu_f(acc);
        }
        __syncthreads();
        for (int i = t; i < 768; i += 256) x[i] = g_sdiff[b][i];
        __syncthreads();
        if (t < 128) {
            float acc = dpb[t];
            for (int j = 0; j < 768; j++) acc += x[j] * dpw[j * 128 + t];
            g_diff[b][t] = telu_f(acc);
        }
    }
}

// ---------------- kernel 9: classifier ----------------
__global__ void __launch_bounds__(128) k_cls(const float* __restrict__ w1, const float* __restrict__ b1,
                                             const float* __restrict__ w2, const float* __restrict__ b2,
                                             float* __restrict__ out) {
    int b = blockIdx.x, t = threadIdx.x;
    __shared__ float comb[512];
    __shared__ float hh[64];
    comb[t] = g_feat[b][t];
    comb[128 + t] = g_diff[b][t];
    comb[256 + t] = g_attnr[b][t];
    comb[384 + t] = g_alignr[b][t];
    __syncthreads();
    if (t < 64) {
        float acc = b1[t];
        for (int j = 0; j < 512; j++) acc += comb[j] * w1[j * 64 + t];
        hh[t] = telu_f(acc);
    }
    __syncthreads();
    if (t < 3) {
        float acc = b2[t];
        for (int j = 0; j < 64; j++) acc += hh[j] * w2[j * 3 + t];
        out[b * 3 + t] = acc;
    }
}

// ---------------- launcher ----------------
extern "C" void kernel_launch(void* const* d_in, const int* in_sizes, int n_in,
                              void* d_out, int out_size) {
    (void)in_sizes; (void)n_in; (void)out_size;
    const float* hs   = (const float*)d_in[0];
    const int*   ids  = (const int*)d_in[1];
    const float* few1 = (const float*)d_in[3];
    const float* feb1 = (const float*)d_in[4];
    const float* feg  = (const float*)d_in[5];
    const float* febe = (const float*)d_in[6];
    const float* few2 = (const float*)d_in[7];
    const float* feb2 = (const float*)d_in[8];
    const float* alw1 = (const float*)d_in[9];
    const float* alb1 = (const float*)d_in[10];
    const float* alw2 = (const float*)d_in[11];
    const float* alb2 = (const float*)d_in[12];
    const float* wq   = (const float*)d_in[13];
    const float* bq   = (const float*)d_in[14];
    const float* wk   = (const float*)d_in[15];
    const float* bk   = (const float*)d_in[16];
    const float* wv   = (const float*)d_in[17];
    const float* bv   = (const float*)d_in[18];
    const float* wo   = (const float*)d_in[19];
    const float* bo   = (const float*)d_in[20];
    const float* dpw  = (const float*)d_in[21];
    const float* dpb  = (const float*)d_in[22];
    const float* apw  = (const float*)d_in[23];
    const float* apb  = (const float*)d_in[24];
    const float* clw1 = (const float*)d_in[25];
    const float* clb1 = (const float*)d_in[26];
    const float* clw2 = (const float*)d_in[27];
    const float* clb2 = (const float*)d_in[28];
    float* out = (float*)d_out;

    k_sep<<<BB, 128>>>(ids);                                      // 1
    k_gemm_qk<<<dim3(6, 4, BB * 2), 256>>>(hs, wq, bq, wk, bk);   // 2
    k_score_fused<<<dim3(16, NHH, BB), 256>>>();                  // 3
    k_gemm_sim<<<dim3(8, 4, BB), 256>>>(hs);                      // 4 <- profiled slot
    k_softmaxw<<<dim3(SCH, 2, BB), 256>>>();                      // 5
    k_stream<<<dim3(6, RCH, BB), 128>>>(hs);                      // 6
    k_finish<<<dim3(6, BB), 128>>>(hs);                           // 7
    k_heads<<<dim3(3, BB), 256>>>(wv, bv, wo, bo, apw, apb,
                                  alw1, alb1, alw2, alb2,
                                  few1, feb1, feg, febe, few2, feb2,
                                  dpw, dpb);                      // 8
    k_cls<<<BB, 128>>>(clw1, clb1, clw2, clb2, out);              // 9
}